// round 2
// baseline (speedup 1.0000x reference)
#include <cuda_runtime.h>
#include <math.h>

#define BB 256
#define TT 256
#define FF 64
#define UU 512
#define GG 2048   // 4*UU

// Persistent state buffers (device globals: no allocation allowed).
// h is double-buffered (cross-CTA read/write race across a step otherwise);
// c is read/written by the same (b,u)-owning thread, single buffer is safe.
__device__ float g_h1[2][BB * UU];
__device__ float g_c1[BB * UU];
__device__ float g_h2[2][BB * UU];
__device__ float g_c2[BB * UU];

__global__ void zero_state_kernel() {
    int i = blockIdx.x * blockDim.x + threadIdx.x;
    if (i < BB * UU) {
        g_h1[0][i] = 0.f;
        g_c1[i]    = 0.f;
        g_h2[0][i] = 0.f;
        g_c2[i]    = 0.f;
    }
}

__device__ __forceinline__ float sigmoidf_(float x) {
    return 1.f / (1.f + expf(-x));
}

// One LSTM step for all 256 batch rows:
//   z = xin @ W + h_prev @ Uw + bias          (gate order i,f,g,o; cols g*512+u)
//   i,f,o = sigmoid; g = relu; c = f*c + i*g; h = o*relu(c)
// CTA tile: 64 batch x 16 hidden units (x4 gates). Thread: 4 batch x 1 unit x 4 gates.
// SMEM: xs[b][k] (x fetch is warp-broadcast), ws[k][u*4+g] (gates contiguous -> LDS.128).
template <int KX>
__global__ __launch_bounds__(256, 1)
void lstm_step_kernel(const float* __restrict__ xin, int ldx,
                      const float* __restrict__ W,      // [KX][2048]
                      const float* __restrict__ Uw,     // [512][2048]
                      const float* __restrict__ bias,   // [2048]
                      const float* __restrict__ hprev,  // [256][512]
                      float* __restrict__ cstate,       // [256][512]
                      float* __restrict__ hnew)         // [256][512]
{
    __shared__ float xs[64][32];
    __shared__ float ws[32][64];

    const int tid = threadIdx.x;
    const int tu  = tid & 15;   // unit within tile
    const int tb  = tid >> 4;   // batch group (4 rows each)
    const int b0  = blockIdx.x * 64;
    const int u0  = blockIdx.y * 16;

    float acc[4][4];
#pragma unroll
    for (int j = 0; j < 4; j++)
#pragma unroll
        for (int g = 0; g < 4; g++) acc[j][g] = 0.f;

    // loader index decompositions
    const int lb = tid >> 5, lk = tid & 31;                 // x loads: 8 rows / pass
    const int wu = tid & 15, wg = (tid >> 4) & 3, wk = tid >> 6;  // w loads: 4 k / pass

#pragma unroll
    for (int seg = 0; seg < 2; seg++) {
        const float* src = seg ? hprev : xin;
        const int    lds = seg ? UU : ldx;
        const float* Wt  = seg ? Uw : W;
        const int    K   = seg ? UU : KX;

        for (int k0 = 0; k0 < K; k0 += 32) {
            __syncthreads();
            // xs[b][k] : warp writes one contiguous 128B row (conflict-free),
            // global read 128B coalesced
#pragma unroll
            for (int p = 0; p < 8; p++)
                xs[lb + p * 8][lk] = src[(b0 + lb + p * 8) * lds + (k0 + lk)];
            // ws[k][u*4+g] = Wt[k][g*512 + u0 + u]
#pragma unroll
            for (int p = 0; p < 8; p++)
                ws[wk + p * 4][wu * 4 + wg] =
                    Wt[(k0 + wk + p * 4) * GG + wg * UU + (u0 + wu)];
            __syncthreads();

#pragma unroll
            for (int k = 0; k < 32; k += 4) {
                const float4 w0 = *(const float4*)&ws[k + 0][tu * 4];
                const float4 w1 = *(const float4*)&ws[k + 1][tu * 4];
                const float4 w2 = *(const float4*)&ws[k + 2][tu * 4];
                const float4 w3 = *(const float4*)&ws[k + 3][tu * 4];
#pragma unroll
                for (int j = 0; j < 4; j++) {
                    const float4 xv = *(const float4*)&xs[tb * 4 + j][k];
                    acc[j][0] = fmaf(xv.x, w0.x, acc[j][0]);
                    acc[j][1] = fmaf(xv.x, w0.y, acc[j][1]);
                    acc[j][2] = fmaf(xv.x, w0.z, acc[j][2]);
                    acc[j][3] = fmaf(xv.x, w0.w, acc[j][3]);
                    acc[j][0] = fmaf(xv.y, w1.x, acc[j][0]);
                    acc[j][1] = fmaf(xv.y, w1.y, acc[j][1]);
                    acc[j][2] = fmaf(xv.y, w1.z, acc[j][2]);
                    acc[j][3] = fmaf(xv.y, w1.w, acc[j][3]);
                    acc[j][0] = fmaf(xv.z, w2.x, acc[j][0]);
                    acc[j][1] = fmaf(xv.z, w2.y, acc[j][1]);
                    acc[j][2] = fmaf(xv.z, w2.z, acc[j][2]);
                    acc[j][3] = fmaf(xv.z, w2.w, acc[j][3]);
                    acc[j][0] = fmaf(xv.w, w3.x, acc[j][0]);
                    acc[j][1] = fmaf(xv.w, w3.y, acc[j][1]);
                    acc[j][2] = fmaf(xv.w, w3.z, acc[j][2]);
                    acc[j][3] = fmaf(xv.w, w3.w, acc[j][3]);
                }
            }
        }
    }

    const int u  = u0 + tu;
    const float bi = bias[0 * UU + u];
    const float bf = bias[1 * UU + u];
    const float bg = bias[2 * UU + u];
    const float bo = bias[3 * UU + u];

#pragma unroll
    for (int j = 0; j < 4; j++) {
        const int b   = b0 + tb * 4 + j;
        const int idx = b * UU + u;
        const float zi = acc[j][0] + bi;
        const float zf = acc[j][1] + bf;
        const float zg = acc[j][2] + bg;
        const float zo = acc[j][3] + bo;
        const float ig = sigmoidf_(zi);
        const float fg = sigmoidf_(zf);
        const float gg = fmaxf(zg, 0.f);
        const float og = sigmoidf_(zo);
        const float c  = fg * cstate[idx] + ig * gg;
        cstate[idx] = c;
        hnew[idx]   = og * fmaxf(c, 0.f);
    }
}

__global__ void head_kernel(const float* __restrict__ h2,
                            const float* __restrict__ Wd,
                            const float* __restrict__ bd,
                            float* __restrict__ out)
{
    const int b = threadIdx.x;  // 256 threads, one batch row each
    float s = 0.f;
#pragma unroll 8
    for (int k = 0; k < UU; k++) s = fmaf(h2[b * UU + k], Wd[k], s);
    out[b] = 1.f / (1.f + expf(-(s + bd[0])));
}

extern "C" void kernel_launch(void* const* d_in, const int* in_sizes, int n_in,
                              void* d_out, int out_size) {
    const float* x  = (const float*)d_in[0];
    const float* W1 = (const float*)d_in[1];
    const float* U1 = (const float*)d_in[2];
    const float* b1 = (const float*)d_in[3];
    const float* W2 = (const float*)d_in[4];
    const float* U2 = (const float*)d_in[5];
    const float* b2 = (const float*)d_in[6];
    const float* Wd = (const float*)d_in[7];
    const float* bd = (const float*)d_in[8];
    float* out = (float*)d_out;

    float *h1b, *c1, *h2b, *c2;
    cudaGetSymbolAddress((void**)&h1b, g_h1);
    cudaGetSymbolAddress((void**)&c1,  g_c1);
    cudaGetSymbolAddress((void**)&h2b, g_h2);
    cudaGetSymbolAddress((void**)&c2,  g_c2);
    float* h1[2] = { h1b, h1b + BB * UU };
    float* h2[2] = { h2b, h2b + BB * UU };

    zero_state_kernel<<<(BB * UU + 255) / 256, 256>>>();

    dim3 grid(BB / 64, UU / 16);  // 4 x 32 = 128 CTAs
    for (int t = 0; t < TT; t++) {
        // layer 1: xin = x[:, t, :] (batch stride T*F), fused input+recurrent GEMM
        lstm_step_kernel<FF><<<grid, 256>>>(x + t * FF, TT * FF, W1, U1, b1,
                                            h1[t & 1], c1, h1[(t + 1) & 1]);
        // layer 2: xin = layer-1's fresh h_t (no h1-sequence materialization)
        lstm_step_kernel<UU><<<grid, 256>>>(h1[(t + 1) & 1], UU, W2, U2, b2,
                                            h2[t & 1], c2, h2[(t + 1) & 1]);
    }
    // after t=255, layer-2 state was written to parity (255+1)&1 = 0
    head_kernel<<<1, 256>>>(h2[0], Wd, bd, out);
}

// round 3
// speedup vs baseline: 1.0014x; 1.0014x over previous
#include <cuda_runtime.h>
#include <math.h>

#define BB 256
#define TT 256
#define FF 64
#define UU 512
#define GG 2048   // 4*UU

// Persistent state buffers (device globals: no allocation allowed).
// h is double-buffered (cross-CTA read/write race across a step otherwise);
// c is read/written by the same (b,u)-owning thread, single buffer is safe.
__device__ float g_h1[2][BB * UU];
__device__ float g_c1[BB * UU];
__device__ float g_h2[2][BB * UU];
__device__ float g_c2[BB * UU];

__global__ void zero_state_kernel() {
    int i = blockIdx.x * blockDim.x + threadIdx.x;
    if (i < BB * UU) {
        g_h1[0][i] = 0.f;
        g_c1[i]    = 0.f;
        g_h2[0][i] = 0.f;
        g_c2[i]    = 0.f;
    }
}

__device__ __forceinline__ float sigmoidf_(float x) {
    return 1.f / (1.f + expf(-x));
}

// One LSTM step for all 256 batch rows:
//   z = xin @ W + h_prev @ Uw + bias          (gate order i,f,g,o; cols g*512+u)
//   i,f,o = sigmoid; g = relu; c = f*c + i*g; h = o*relu(c)
// CTA tile: 64 batch x 16 hidden units (x4 gates). Thread: 4 batch x 1 unit x 4 gates.
// SMEM: xs[b][k] (x fetch is warp-broadcast), ws[k][u*4+g] (gates contiguous -> LDS.128).
template <int KX>
__global__ __launch_bounds__(256, 1)
void lstm_step_kernel(const float* __restrict__ xin, int ldx,
                      const float* __restrict__ W,      // [KX][2048]
                      const float* __restrict__ Uw,     // [512][2048]
                      const float* __restrict__ bias,   // [2048]
                      const float* __restrict__ hprev,  // [256][512]
                      float* __restrict__ cstate,       // [256][512]
                      float* __restrict__ hnew)         // [256][512]
{
    __shared__ float xs[64][32];
    __shared__ float ws[32][64];

    const int tid = threadIdx.x;
    const int tu  = tid & 15;   // unit within tile
    const int tb  = tid >> 4;   // batch group (4 rows each)
    const int b0  = blockIdx.x * 64;
    const int u0  = blockIdx.y * 16;

    float acc[4][4];
#pragma unroll
    for (int j = 0; j < 4; j++)
#pragma unroll
        for (int g = 0; g < 4; g++) acc[j][g] = 0.f;

    // loader index decompositions
    const int lb = tid >> 5, lk = tid & 31;                 // x loads: 8 rows / pass
    const int wu = tid & 15, wg = (tid >> 4) & 3, wk = tid >> 6;  // w loads: 4 k / pass

#pragma unroll
    for (int seg = 0; seg < 2; seg++) {
        const float* src = seg ? hprev : xin;
        const int    lds = seg ? UU : ldx;
        const float* Wt  = seg ? Uw : W;
        const int    K   = seg ? UU : KX;

        for (int k0 = 0; k0 < K; k0 += 32) {
            __syncthreads();
            // xs[b][k] : warp writes one contiguous 128B row (conflict-free),
            // global read 128B coalesced
#pragma unroll
            for (int p = 0; p < 8; p++)
                xs[lb + p * 8][lk] = src[(b0 + lb + p * 8) * lds + (k0 + lk)];
            // ws[k][u*4+g] = Wt[k][g*512 + u0 + u]
#pragma unroll
            for (int p = 0; p < 8; p++)
                ws[wk + p * 4][wu * 4 + wg] =
                    Wt[(k0 + wk + p * 4) * GG + wg * UU + (u0 + wu)];
            __syncthreads();

#pragma unroll
            for (int k = 0; k < 32; k += 4) {
                const float4 w0 = *(const float4*)&ws[k + 0][tu * 4];
                const float4 w1 = *(const float4*)&ws[k + 1][tu * 4];
                const float4 w2 = *(const float4*)&ws[k + 2][tu * 4];
                const float4 w3 = *(const float4*)&ws[k + 3][tu * 4];
#pragma unroll
                for (int j = 0; j < 4; j++) {
                    const float4 xv = *(const float4*)&xs[tb * 4 + j][k];
                    acc[j][0] = fmaf(xv.x, w0.x, acc[j][0]);
                    acc[j][1] = fmaf(xv.x, w0.y, acc[j][1]);
                    acc[j][2] = fmaf(xv.x, w0.z, acc[j][2]);
                    acc[j][3] = fmaf(xv.x, w0.w, acc[j][3]);
                    acc[j][0] = fmaf(xv.y, w1.x, acc[j][0]);
                    acc[j][1] = fmaf(xv.y, w1.y, acc[j][1]);
                    acc[j][2] = fmaf(xv.y, w1.z, acc[j][2]);
                    acc[j][3] = fmaf(xv.y, w1.w, acc[j][3]);
                    acc[j][0] = fmaf(xv.z, w2.x, acc[j][0]);
                    acc[j][1] = fmaf(xv.z, w2.y, acc[j][1]);
                    acc[j][2] = fmaf(xv.z, w2.z, acc[j][2]);
                    acc[j][3] = fmaf(xv.z, w2.w, acc[j][3]);
                    acc[j][0] = fmaf(xv.w, w3.x, acc[j][0]);
                    acc[j][1] = fmaf(xv.w, w3.y, acc[j][1]);
                    acc[j][2] = fmaf(xv.w, w3.z, acc[j][2]);
                    acc[j][3] = fmaf(xv.w, w3.w, acc[j][3]);
                }
            }
        }
    }

    const int u  = u0 + tu;
    const float bi = bias[0 * UU + u];
    const float bf = bias[1 * UU + u];
    const float bg = bias[2 * UU + u];
    const float bo = bias[3 * UU + u];

#pragma unroll
    for (int j = 0; j < 4; j++) {
        const int b   = b0 + tb * 4 + j;
        const int idx = b * UU + u;
        const float zi = acc[j][0] + bi;
        const float zf = acc[j][1] + bf;
        const float zg = acc[j][2] + bg;
        const float zo = acc[j][3] + bo;
        const float ig = sigmoidf_(zi);
        const float fg = sigmoidf_(zf);
        const float gg = fmaxf(zg, 0.f);
        const float og = sigmoidf_(zo);
        const float c  = fg * cstate[idx] + ig * gg;
        cstate[idx] = c;
        hnew[idx]   = og * fmaxf(c, 0.f);
    }
}

__global__ void head_kernel(const float* __restrict__ h2,
                            const float* __restrict__ Wd,
                            const float* __restrict__ bd,
                            float* __restrict__ out)
{
    const int b = threadIdx.x;  // 256 threads, one batch row each
    float s = 0.f;
#pragma unroll 8
    for (int k = 0; k < UU; k++) s = fmaf(h2[b * UU + k], Wd[k], s);
    out[b] = 1.f / (1.f + expf(-(s + bd[0])));
}

extern "C" void kernel_launch(void* const* d_in, const int* in_sizes, int n_in,
                              void* d_out, int out_size) {
    const float* x  = (const float*)d_in[0];
    const float* W1 = (const float*)d_in[1];
    const float* U1 = (const float*)d_in[2];
    const float* b1 = (const float*)d_in[3];
    const float* W2 = (const float*)d_in[4];
    const float* U2 = (const float*)d_in[5];
    const float* b2 = (const float*)d_in[6];
    const float* Wd = (const float*)d_in[7];
    const float* bd = (const float*)d_in[8];
    float* out = (float*)d_out;

    float *h1b, *c1, *h2b, *c2;
    cudaGetSymbolAddress((void**)&h1b, g_h1);
    cudaGetSymbolAddress((void**)&c1,  g_c1);
    cudaGetSymbolAddress((void**)&h2b, g_h2);
    cudaGetSymbolAddress((void**)&c2,  g_c2);
    float* h1[2] = { h1b, h1b + BB * UU };
    float* h2[2] = { h2b, h2b + BB * UU };

    zero_state_kernel<<<(BB * UU + 255) / 256, 256>>>();

    dim3 grid(BB / 64, UU / 16);  // 4 x 32 = 128 CTAs
    for (int t = 0; t < TT; t++) {
        // layer 1: xin = x[:, t, :] (batch stride T*F), fused input+recurrent GEMM
        lstm_step_kernel<FF><<<grid, 256>>>(x + t * FF, TT * FF, W1, U1, b1,
                                            h1[t & 1], c1, h1[(t + 1) & 1]);
        // layer 2: xin = layer-1's fresh h_t (no h1-sequence materialization)
        lstm_step_kernel<UU><<<grid, 256>>>(h1[(t + 1) & 1], UU, W2, U2, b2,
                                            h2[t & 1], c2, h2[(t + 1) & 1]);
    }
    // after t=255, layer-2 state was written to parity (255+1)&1 = 0
    head_kernel<<<1, 256>>>(h2[0], Wd, bd, out);
}

// round 5
// speedup vs baseline: 1.5366x; 1.5344x over previous
#include <cuda_runtime.h>
#include <mma.h>
#include <math.h>
#include <stdint.h>

using namespace nvcuda;

#define BB 256
#define TT 256
#define FF 64
#define UU 512
#define GG 2048

#define NTILES 32      // 32 unit-tiles of 16 units; CTA N = 4 gates x 16 units = 64
#define NCOL   64
#define KC     32      // K per chunk
#define STAGES 3

#define LDA 72         // A smem stride (floats), padded
#define LDB 68         // B smem stride (floats), padded
#define A_STG (64 * LDA * 4)            // 18432 B
#define B_STG (KC * LDB * 4)            // 8704 B
#define A_OFF 0
#define B_OFF (STAGES * A_STG)          // 55296
#define BIAS_OFF (B_OFF + STAGES * B_STG)   // 81408
#define SMEM_BYTES (BIAS_OFF + 256 + 128)

__device__ float g_xT[TT * BB * FF];        // [t][b][f], tf32-rounded
__device__ float g_img1[NTILES * 576 * NCOL];   // [tile][chunk][k][n] packed
__device__ float g_img2[NTILES * 1024 * NCOL];
__device__ float g_h1[2][BB * UU];
__device__ float g_c1[BB * UU];
__device__ float g_h2[2][BB * UU];
__device__ float g_c2[BB * UU];

__device__ __forceinline__ float rna_tf32(float x) {
    uint32_t r;
    asm("cvt.rna.tf32.f32 %0, %1;" : "=r"(r) : "f"(x));
    return __uint_as_float(r);
}
__device__ __forceinline__ float sigmoidf_(float x) { return 1.f / (1.f + expf(-x)); }

#define CP_ASYNC16(dst, src) \
    asm volatile("cp.async.cg.shared.global [%0], [%1], 16;" :: "r"(dst), "l"(src))
#define CP_COMMIT() asm volatile("cp.async.commit_group;" ::: "memory")
#define CP_WAIT1()  asm volatile("cp.async.wait_group 1;" ::: "memory")

__global__ void zero_state_kernel() {
    int i = blockIdx.x * blockDim.x + threadIdx.x;
    if (i < BB * UU) { g_h1[0][i] = 0.f; g_c1[i] = 0.f; g_h2[0][i] = 0.f; g_c2[i] = 0.f; }
}

__global__ void prep_x_kernel(const float* __restrict__ x) {
    int e = blockIdx.x * blockDim.x + threadIdx.x;   // e = b*T*F + t*F + f
    if (e >= BB * TT * FF) return;
    int f = e & 63, t = (e >> 6) & 255, b = e >> 14;
    g_xT[t * (BB * FF) + b * FF + f] = rna_tf32(x[e]);
}

// Weight image: per unit-tile, per 32-K chunk, packed [k][n] (n = g*16+ui -> col g*512+tile*16+ui).
// K rows = [W (KW rows); U (rest)], all tf32-rounded. Per-step ingest is a verbatim copy.
__global__ void prep_img_kernel(const float* __restrict__ Wm, const float* __restrict__ Um,
                                float* __restrict__ img, int KW, int Ktot) {
    int e = blockIdx.x * blockDim.x + threadIdx.x;
    if (e >= NTILES * Ktot * NCOL) return;
    int n = e & 63;
    int k = (e >> 6) % Ktot;
    int tile = e / (Ktot * NCOL);
    int g = n >> 4, ui = n & 15;
    int col = g * UU + tile * 16 + ui;
    float v = (k < KW) ? Wm[k * GG + col] : Um[(k - KW) * GG + col];
    img[tile * (Ktot * NCOL) + (k >> 5) * (KC * NCOL) + (k & 31) * NCOL + n] = rna_tf32(v);
}

// grid (4, 32), block 128 (4 warps, 2x2): z[64b x 64n] = [A0|A1][64,K] @ Wtile[K,64]
// via wmma tf32 m16n16k8. Epilogue stages z through smem for the c/h update.
__global__ void __launch_bounds__(128, 1)
lstm_step_mma(const float* __restrict__ src0, int ld0, int csplit,
              const float* __restrict__ src1,
              const float* __restrict__ img, int imgTileFloats, int C,
              const float* __restrict__ bias,
              float* __restrict__ cstate,
              float* __restrict__ hout)
{
    extern __shared__ __align__(1024) char smem[];
    uint32_t sb = (uint32_t)__cvta_generic_to_shared(smem);
    float* As = (float*)smem;                 // per stage: [64][LDA]
    float* Bs = (float*)(smem + B_OFF);       // per stage: [KC][LDB]
    float* bsm = (float*)(smem + BIAS_OFF);

    const int tid = threadIdx.x, wid = tid >> 5;
    const int bM = blockIdx.x * 64, tile = blockIdx.y;
    const int w_m = wid & 1, w_n = wid >> 1;  // warp tile 32x32 at (w_m*32, w_n*32)

    if (tid < 64) {
        int g = tid >> 4, ui = tid & 15;
        bsm[tid] = bias[g * UU + tile * 16 + ui];
    }

    const char* imgb = (const char*)(img + (size_t)tile * imgTileFloats);

    auto load_chunk = [&](int c, int slot) {
        // A: 64 rows x 32 floats -> [m][LDA]
        const float* as; int lda, k0;
        if (c < csplit) { as = src0; lda = ld0; k0 = c * KC; }
        else            { as = src1; lda = UU;  k0 = (c - csplit) * KC; }
        uint32_t adst = sb + A_OFF + slot * A_STG;
#pragma unroll
        for (int j = 0; j < 4; j++) {
            int u = tid + 128 * j, m = u >> 3, kq = u & 7;
            CP_ASYNC16(adst + (uint32_t)(m * (LDA * 4) + kq * 16),
                       as + (size_t)(bM + m) * lda + k0 + kq * 4);
        }
        // B: verbatim packed [k 32][n 64] -> [k][LDB]
        const char* wsrc = imgb + (size_t)c * (KC * NCOL * 4);
        uint32_t bdst = sb + B_OFF + slot * B_STG;
#pragma unroll
        for (int j = 0; j < 4; j++) {
            int u = tid + 128 * j, k = u >> 4, nq = u & 15;
            CP_ASYNC16(bdst + (uint32_t)(k * (LDB * 4) + nq * 16), wsrc + u * 16);
        }
        CP_COMMIT();
    };

    wmma::fragment<wmma::accumulator, 16, 16, 8, float> acc[2][2];
#pragma unroll
    for (int i = 0; i < 2; i++)
#pragma unroll
        for (int j = 0; j < 2; j++) wmma::fill_fragment(acc[i][j], 0.f);

    for (int p = 0; p < STAGES - 1; p++) load_chunk(p, p);

#pragma unroll 1
    for (int i = 0; i < C; i++) {
        CP_WAIT1();          // chunk i's copies done (own thread)
        __syncthreads();     // -> CTA-wide; also protects slot reuse
        const float* Ab = As + (i % STAGES) * (A_STG / 4);
        const float* Bb = Bs + (i % STAGES) * (B_STG / 4);
#pragma unroll
        for (int ks = 0; ks < 4; ks++) {
            const int kof = ks * 8;
            wmma::fragment<wmma::matrix_a, 16, 16, 8, wmma::precision::tf32, wmma::row_major> af[2];
            wmma::fragment<wmma::matrix_b, 16, 16, 8, wmma::precision::tf32, wmma::row_major> bf[2];
#pragma unroll
            for (int q = 0; q < 2; q++)
                wmma::load_matrix_sync(af[q], Ab + (w_m * 32 + 16 * q) * LDA + kof, LDA);
#pragma unroll
            for (int q = 0; q < 2; q++)
                wmma::load_matrix_sync(bf[q], Bb + kof * LDB + (w_n * 32 + 16 * q), LDB);
#pragma unroll
            for (int q = 0; q < 2; q++)
#pragma unroll
                for (int r = 0; r < 2; r++)
                    wmma::mma_sync(acc[q][r], af[q], bf[r], acc[q][r]);
        }
        __syncthreads();
        int nc = i + STAGES - 1;
        if (nc < C) load_chunk(nc, nc % STAGES);
        else        CP_COMMIT();   // empty group keeps wait_group accounting aligned
    }

    // ---- epilogue: stage z[64][64] in smem (overlay A stage 0), then gate math ----
    __syncthreads();
    float* zs = (float*)smem;   // [64][LDA]
#pragma unroll
    for (int q = 0; q < 2; q++)
#pragma unroll
        for (int r = 0; r < 2; r++)
            wmma::store_matrix_sync(zs + (w_m * 32 + 16 * q) * LDA + (w_n * 32 + 16 * r),
                                    acc[q][r], LDA, wmma::mem_row_major);
    __syncthreads();

    const int u  = tid & 15;        // unit within tile
    const int b8 = tid >> 4;        // batch octet
    const int u0 = tile * 16;
    const float bi = bsm[u], bf_ = bsm[16 + u], bg = bsm[32 + u], bo = bsm[48 + u];

#pragma unroll
    for (int j = 0; j < 8; j++) {
        const int m = b8 * 8 + j;               // local batch row 0..63
        const int idx = (size_t)(bM + m) * UU + u0 + u;
        const float zi = zs[m * LDA + u]       + bi;
        const float zf = zs[m * LDA + 16 + u]  + bf_;
        const float zg = zs[m * LDA + 32 + u]  + bg;
        const float zo = zs[m * LDA + 48 + u]  + bo;
        const float ig = sigmoidf_(zi);
        const float fg = sigmoidf_(zf);
        const float gg = fmaxf(zg, 0.f);
        const float og = sigmoidf_(zo);
        const float c  = fg * cstate[idx] + ig * gg;
        cstate[idx] = c;
        hout[idx]   = rna_tf32(og * fmaxf(c, 0.f));  // next-step MMA input exact tf32
    }
}

__global__ void head_kernel(const float* __restrict__ h2,
                            const float* __restrict__ Wd,
                            const float* __restrict__ bd,
                            float* __restrict__ out)
{
    const int b = threadIdx.x;
    float s = 0.f;
#pragma unroll 8
    for (int k = 0; k < UU; k++) s = fmaf(h2[b * UU + k], Wd[k], s);
    out[b] = 1.f / (1.f + expf(-(s + bd[0])));
}

extern "C" void kernel_launch(void* const* d_in, const int* in_sizes, int n_in,
                              void* d_out, int out_size) {
    const float* x  = (const float*)d_in[0];
    const float* W1 = (const float*)d_in[1];
    const float* U1 = (const float*)d_in[2];
    const float* b1 = (const float*)d_in[3];
    const float* W2 = (const float*)d_in[4];
    const float* U2 = (const float*)d_in[5];
    const float* b2 = (const float*)d_in[6];
    const float* Wd = (const float*)d_in[7];
    const float* bd = (const float*)d_in[8];
    float* out = (float*)d_out;

    cudaFuncSetAttribute(lstm_step_mma, cudaFuncAttributeMaxDynamicSharedMemorySize, SMEM_BYTES);

    float *xT, *img1, *img2, *h1b, *c1, *h2b, *c2;
    cudaGetSymbolAddress((void**)&xT,   g_xT);
    cudaGetSymbolAddress((void**)&img1, g_img1);
    cudaGetSymbolAddress((void**)&img2, g_img2);
    cudaGetSymbolAddress((void**)&h1b,  g_h1);
    cudaGetSymbolAddress((void**)&c1,   g_c1);
    cudaGetSymbolAddress((void**)&h2b,  g_h2);
    cudaGetSymbolAddress((void**)&c2,   g_c2);
    float* h1[2] = { h1b, h1b + BB * UU };
    float* h2[2] = { h2b, h2b + BB * UU };

    zero_state_kernel<<<(BB * UU + 255) / 256, 256>>>();
    prep_x_kernel<<<(BB * TT * FF + 255) / 256, 256>>>(x);
    prep_img_kernel<<<(NTILES * 576 * NCOL + 255) / 256, 256>>>(W1, U1, img1, FF, 576);
    prep_img_kernel<<<(NTILES * 1024 * NCOL + 255) / 256, 256>>>(W2, U2, img2, UU, 1024);

    dim3 grid(BB / 64, NTILES);  // 4 x 32 = 128 CTAs
    for (int t = 0; t < TT; t++) {
        lstm_step_mma<<<grid, 128, SMEM_BYTES>>>(
            xT + t * BB * FF, FF, 2, h1[t & 1],
            img1, 576 * NCOL, 18, b1, c1, h1[(t + 1) & 1]);
        lstm_step_mma<<<grid, 128, SMEM_BYTES>>>(
            h1[(t + 1) & 1], UU, 16, h2[t & 1],
            img2, 1024 * NCOL, 32, b2, c2, h2[(t + 1) & 1]);
    }
    head_kernel<<<1, 256>>>(h2[0], Wd, bd, out);
}

// round 9
// speedup vs baseline: 1.6113x; 1.0486x over previous
#include <cuda_runtime.h>
#include <mma.h>
#include <math.h>
#include <stdint.h>

using namespace nvcuda;

#define BB 256
#define TT 256
#define FF 64
#define UU 512
#define GG 2048

#define NTILES 32      // 32 unit-tiles of 16 units; CTA N = 4 gates x 16 units = 64
#define NCOL   64
#define KC     64      // K per chunk (8 k8-slices)
#define STAGES 3

#define LDA 72         // A smem stride (floats), padded (64+8)
#define LDB 72         // B smem stride (floats), padded
#define A_STG (64 * LDA * 4)            // 18432 B  ([m 64][k 64])
#define B_STG (KC * LDB * 4)            // 18432 B  ([k 64][n 64])
#define A_OFF 0
#define B_OFF (STAGES * A_STG)
#define BIAS_OFF (B_OFF + STAGES * B_STG)
#define SMEM_BYTES (BIAS_OFF + 256 + 128)

__device__ float g_xT[TT * BB * FF];            // [t][b][f], tf32-rounded
__device__ float g_img1[NTILES * 576 * NCOL];   // [tile][chunk64][k][n] packed
__device__ float g_img2[NTILES * 1024 * NCOL];
__device__ float g_h1[2][BB * UU];
__device__ float g_c1[BB * UU];
__device__ float g_h2[2][BB * UU];
__device__ float g_c2[BB * UU];

__device__ __forceinline__ float rna_tf32(float x) {
    uint32_t r;
    asm("cvt.rna.tf32.f32 %0, %1;" : "=r"(r) : "f"(x));
    return __uint_as_float(r);
}
__device__ __forceinline__ float sigmoidf_(float x) { return 1.f / (1.f + expf(-x)); }

#define CP_ASYNC16(dst, src) \
    asm volatile("cp.async.cg.shared.global [%0], [%1], 16;" :: "r"(dst), "l"(src))
#define CP_COMMIT() asm volatile("cp.async.commit_group;" ::: "memory")
#define CP_WAIT1()  asm volatile("cp.async.wait_group 1;" ::: "memory")

__global__ void zero_state_kernel() {
    int i = blockIdx.x * blockDim.x + threadIdx.x;
    if (i < BB * UU) { g_h1[0][i] = 0.f; g_c1[i] = 0.f; g_h2[0][i] = 0.f; g_c2[i] = 0.f; }
}

__global__ void prep_x_kernel(const float* __restrict__ x) {
    int e = blockIdx.x * blockDim.x + threadIdx.x;   // e = b*T*F + t*F + f
    if (e >= BB * TT * FF) return;
    int f = e & 63, t = (e >> 6) & 255, b = e >> 14;
    g_xT[t * (BB * FF) + b * FF + f] = rna_tf32(x[e]);
}

// Weight image: per unit-tile, per 64-K chunk, packed [k][n] (n=g*16+ui -> col g*512+tile*16+ui).
// K rows = [W (KW rows); U (rest)], tf32-rounded. Per-step ingest is a verbatim copy.
__global__ void prep_img_kernel(const float* __restrict__ Wm, const float* __restrict__ Um,
                                float* __restrict__ img, int KW, int Ktot) {
    int e = blockIdx.x * blockDim.x + threadIdx.x;
    if (e >= NTILES * Ktot * NCOL) return;
    int n = e & 63;
    int k = (e >> 6) % Ktot;
    int tile = e / (Ktot * NCOL);
    int g = n >> 4, ui = n & 15;
    int col = g * UU + tile * 16 + ui;
    float v = (k < KW) ? Wm[k * GG + col] : Um[(k - KW) * GG + col];
    img[tile * (Ktot * NCOL) + (k >> 6) * (KC * NCOL) + (k & 63) * NCOL + n] = rna_tf32(v);
}

// grid (4, 32), block 128 (4 warps, 2x2): z[64b x 64n] = [A0|A1][64,K] @ Wtile[K,64]
// via wmma tf32 m16n16k8; 3-stage cp.async pipeline, ONE __syncthreads per 64-K chunk.
__global__ void __launch_bounds__(128, 1)
lstm_step_mma(const float* __restrict__ src0, int ld0, int csplit,
              const float* __restrict__ src1,
              const float* __restrict__ img, int imgTileFloats, int C,
              const float* __restrict__ bias,
              float* __restrict__ cstate,
              float* __restrict__ hout)
{
    extern __shared__ __align__(1024) char smem[];
    uint32_t sb = (uint32_t)__cvta_generic_to_shared(smem);
    float* As = (float*)smem;                 // per stage: [64][LDA]
    float* Bs = (float*)(smem + B_OFF);       // per stage: [KC][LDB]
    float* bsm = (float*)(smem + BIAS_OFF);

    const int tid = threadIdx.x, wid = tid >> 5;
    const int bM = blockIdx.x * 64, tile = blockIdx.y;
    const int w_m = wid & 1, w_n = wid >> 1;  // warp tile 32x32 at (w_m*32, w_n*32)

    if (tid < 64) {
        int g = tid >> 4, ui = tid & 15;
        bsm[tid] = bias[g * UU + tile * 16 + ui];
    }

    const char* imgb = (const char*)(img + (size_t)tile * imgTileFloats);

    auto load_chunk = [&](int c, int slot) {
        // A: 64 rows x 64 floats -> [m][LDA]
        const float* as; int lda, k0;
        if (c < csplit) { as = src0; lda = ld0; k0 = c * KC; }
        else            { as = src1; lda = UU;  k0 = (c - csplit) * KC; }
        uint32_t adst = sb + A_OFF + slot * A_STG;
#pragma unroll
        for (int j = 0; j < 8; j++) {
            int u = tid + 128 * j, m = u >> 4, kq = u & 15;
            CP_ASYNC16(adst + (uint32_t)(m * (LDA * 4) + kq * 16),
                       as + (size_t)(bM + m) * lda + k0 + kq * 4);
        }
        // B: verbatim packed [k 64][n 64] -> [k][LDB]
        const char* wsrc = imgb + (size_t)c * (KC * NCOL * 4);
        uint32_t bdst = sb + B_OFF + slot * B_STG;
#pragma unroll
        for (int j = 0; j < 8; j++) {
            int u = tid + 128 * j, k = u >> 4, nq = u & 15;
            CP_ASYNC16(bdst + (uint32_t)(k * (LDB * 4) + nq * 16), wsrc + u * 16);
        }
        CP_COMMIT();
    };

    wmma::fragment<wmma::accumulator, 16, 16, 8, float> acc[2][2];
#pragma unroll
    for (int i = 0; i < 2; i++)
#pragma unroll
        for (int j = 0; j < 2; j++) wmma::fill_fragment(acc[i][j], 0.f);

    load_chunk(0, 0);
    load_chunk(1, 1);

#pragma unroll 1
    for (int i = 0; i < C; i++) {
        CP_WAIT1();          // chunk i's group complete (<=1 outstanding: chunk i+1)
        __syncthreads();     // CTA-wide data ready; also: slot (i-1)%3 fully consumed
        int nc = i + 2;
        if (nc < C) load_chunk(nc, nc % STAGES);   // into slot (i-1)%3 — safe post-sync
        else        CP_COMMIT();                    // keep group accounting aligned

        const float* Ab = As + (i % STAGES) * (A_STG / 4);
        const float* Bb = Bs + (i % STAGES) * (B_STG / 4);
#pragma unroll
        for (int ks = 0; ks < 8; ks++) {
            const int kof = ks * 8;
            wmma::fragment<wmma::matrix_a, 16, 16, 8, wmma::precision::tf32, wmma::row_major> af[2];
            wmma::fragment<wmma::matrix_b, 16, 16, 8, wmma::precision::tf32, wmma::row_major> bf[2];
#pragma unroll
            for (int q = 0; q < 2; q++)
                wmma::load_matrix_sync(af[q], Ab + (w_m * 32 + 16 * q) * LDA + kof, LDA);
#pragma unroll
            for (int q = 0; q < 2; q++)
                wmma::load_matrix_sync(bf[q], Bb + kof * LDB + (w_n * 32 + 16 * q), LDB);
#pragma unroll
            for (int q = 0; q < 2; q++)
#pragma unroll
                for (int r = 0; r < 2; r++)
                    wmma::mma_sync(acc[q][r], af[q], bf[r], acc[q][r]);
        }
    }

    // ---- epilogue: stage z[64][64] in smem (overlay A stage 0), then gate math ----
    __syncthreads();
    float* zs = (float*)smem;   // [64][LDA]
#pragma unroll
    for (int q = 0; q < 2; q++)
#pragma unroll
        for (int r = 0; r < 2; r++)
            wmma::store_matrix_sync(zs + (w_m * 32 + 16 * q) * LDA + (w_n * 32 + 16 * r),
                                    acc[q][r], LDA, wmma::mem_row_major);
    __syncthreads();

    const int u  = tid & 15;        // unit within tile
    const int b8 = tid >> 4;        // batch octet
    const int u0 = tile * 16;
    const float bi = bsm[u], bf_ = bsm[16 + u], bg = bsm[32 + u], bo = bsm[48 + u];

#pragma unroll
    for (int j = 0; j < 8; j++) {
        const int m = b8 * 8 + j;               // local batch row 0..63
        const int idx = (size_t)(bM + m) * UU + u0 + u;
        const float zi = zs[m * LDA + u]       + bi;
        const float zf = zs[m * LDA + 16 + u]  + bf_;
        const float zg = zs[m * LDA + 32 + u]  + bg;
        const float zo = zs[m * LDA + 48 + u]  + bo;
        const float ig = sigmoidf_(zi);
        const float fg = sigmoidf_(zf);
        const float gg = fmaxf(zg, 0.f);
        const float og = sigmoidf_(zo);
        const float c  = fg * cstate[idx] + ig * gg;
        cstate[idx] = c;
        hout[idx]   = rna_tf32(og * fmaxf(c, 0.f));  // next-step MMA input exact tf32
    }
}

__global__ void head_kernel(const float* __restrict__ h2,
                            const float* __restrict__ Wd,
                            const float* __restrict__ bd,
                            float* __restrict__ out)
{
    const int b = threadIdx.x;
    float s = 0.f;
#pragma unroll 8
    for (int k = 0; k < UU; k++) s = fmaf(h2[b * UU + k], Wd[k], s);
    out[b] = 1.f / (1.f + expf(-(s + bd[0])));
}

extern "C" void kernel_launch(void* const* d_in, const int* in_sizes, int n_in,
                              void* d_out, int out_size) {
    const float* x  = (const float*)d_in[0];
    const float* W1 = (const float*)d_in[1];
    const float* U1 = (const float*)d_in[2];
    const float* b1 = (const float*)d_in[3];
    const float* W2 = (const float*)d_in[4];
    const float* U2 = (const float*)d_in[5];
    const float* b2 = (const float*)d_in[6];
    const float* Wd = (const float*)d_in[7];
    const float* bd = (const float*)d_in[8];
    float* out = (float*)d_out;

    cudaFuncSetAttribute(lstm_step_mma, cudaFuncAttributeMaxDynamicSharedMemorySize, SMEM_BYTES);

    float *xT, *img1, *img2, *h1b, *c1, *h2b, *c2;
    cudaGetSymbolAddress((void**)&xT,   g_xT);
    cudaGetSymbolAddress((void**)&img1, g_img1);
    cudaGetSymbolAddress((void**)&img2, g_img2);
    cudaGetSymbolAddress((void**)&h1b,  g_h1);
    cudaGetSymbolAddress((void**)&c1,   g_c1);
    cudaGetSymbolAddress((void**)&h2b,  g_h2);
    cudaGetSymbolAddress((void**)&c2,   g_c2);
    float* h1[2] = { h1b, h1b + BB * UU };
    float* h2[2] = { h2b, h2b + BB * UU };

    zero_state_kernel<<<(BB * UU + 255) / 256, 256>>>();
    prep_x_kernel<<<(BB * TT * FF + 255) / 256, 256>>>(x);
    prep_img_kernel<<<(NTILES * 576 * NCOL + 255) / 256, 256>>>(W1, U1, img1, FF, 576);
    prep_img_kernel<<<(NTILES * 1024 * NCOL + 255) / 256, 256>>>(W2, U2, img2, UU, 1024);

    dim3 grid(BB / 64, NTILES);  // 4 x 32 = 128 CTAs
    for (int t = 0; t < TT; t++) {
        lstm_step_mma<<<grid, 128, SMEM_BYTES>>>(
            xT + t * BB * FF, FF, 1, h1[t & 1],
            img1, 576 * NCOL, 9, b1, c1, h1[(t + 1) & 1]);
        lstm_step_mma<<<grid, 128, SMEM_BYTES>>>(
            h1[(t + 1) & 1], UU, 8, h2[t & 1],
            img2, 1024 * NCOL, 16, b2, c2, h2[(t + 1) & 1]);
    }
    head_kernel<<<1, 256>>>(h2[0], Wd, bd, out);
}

// round 10
// speedup vs baseline: 3.0228x; 1.8761x over previous
#include <cuda_runtime.h>
#include <cuda_bf16.h>
#include <mma.h>
#include <math.h>
#include <stdint.h>

using namespace nvcuda;

#define BB 256
#define TT 256
#define FF 64
#define UU 512
#define GG 2048

#define NTILES 32      // 32 unit-tiles of 16 units; CTA N = 4 gates x 16 units = 64
#define NCOL   64
#define KC     64      // K per chunk (4 k16-slices)
#define STAGES 3

#define LDA 72         // A smem stride (halfs), 144 B/row (16B-multiple, bank-skewed)
#define LDB 72         // B smem stride (halfs)
#define LDZ 72         // z smem stride (floats) for epilogue staging
#define A_STG (64 * LDA * 2)            // 9216 B  ([m 64][k 64] bf16)
#define B_STG (KC * LDB * 2)            // 9216 B  ([k 64][n 64] bf16)
#define A_OFF 0
#define B_OFF (STAGES * A_STG)          // 27648
#define BIAS_OFF (B_OFF + STAGES * B_STG)   // 55296
#define SMEM_BYTES (BIAS_OFF + 256 + 128)

typedef __nv_bfloat16 bf16;

__device__ bf16  g_xT[TT * BB * FF];            // [t][b][f], bf16-rounded
__device__ bf16  g_img1[NTILES * 576 * NCOL];   // [tile][chunk64][k][n] packed bf16
__device__ bf16  g_img2[NTILES * 1024 * NCOL];
__device__ bf16  g_h1[2][BB * UU];
__device__ float g_c1[BB * UU];
__device__ bf16  g_h2[2][BB * UU];
__device__ float g_c2[BB * UU];

__device__ __forceinline__ float sigmoidf_(float x) { return 1.f / (1.f + expf(-x)); }

#define CP_ASYNC16(dst, src) \
    asm volatile("cp.async.cg.shared.global [%0], [%1], 16;" :: "r"(dst), "l"(src))
#define CP_COMMIT() asm volatile("cp.async.commit_group;" ::: "memory")
#define CP_WAIT1()  asm volatile("cp.async.wait_group 1;" ::: "memory")

__global__ void zero_state_kernel() {
    int i = blockIdx.x * blockDim.x + threadIdx.x;
    if (i < BB * UU) {
        g_h1[0][i] = __float2bfloat16_rn(0.f);
        g_h2[0][i] = __float2bfloat16_rn(0.f);
        g_c1[i] = 0.f;
        g_c2[i] = 0.f;
    }
}

__global__ void prep_x_kernel(const float* __restrict__ x) {
    int e = blockIdx.x * blockDim.x + threadIdx.x;   // e = b*T*F + t*F + f
    if (e >= BB * TT * FF) return;
    int f = e & 63, t = (e >> 6) & 255, b = e >> 14;
    g_xT[t * (BB * FF) + b * FF + f] = __float2bfloat16_rn(x[e]);
}

// Weight image: per unit-tile, per 64-K chunk, packed [k][n] (n=g*16+ui -> col g*512+tile*16+ui).
// K rows = [W (KW rows); U (rest)], bf16-rounded. Per-step ingest is a verbatim copy.
__global__ void prep_img_kernel(const float* __restrict__ Wm, const float* __restrict__ Um,
                                bf16* __restrict__ img, int KW, int Ktot) {
    int e = blockIdx.x * blockDim.x + threadIdx.x;
    if (e >= NTILES * Ktot * NCOL) return;
    int n = e & 63;
    int k = (e >> 6) % Ktot;
    int tile = e / (Ktot * NCOL);
    int g = n >> 4, ui = n & 15;
    int col = g * UU + tile * 16 + ui;
    float v = (k < KW) ? Wm[k * GG + col] : Um[(k - KW) * GG + col];
    img[tile * (Ktot * NCOL) + (k >> 6) * (KC * NCOL) + (k & 63) * NCOL + n] =
        __float2bfloat16_rn(v);
}

// grid (4, 32), block 128 (4 warps, 2x2): z[64b x 64n] = [A0|A1][64,K] @ Wtile[K,64]
// via wmma bf16 m16n16k16 (LDSM fragment loads); 3-stage cp.async, 1 sync/chunk.
__global__ void __launch_bounds__(128, 1)
lstm_step_mma(const bf16* __restrict__ src0, int ld0, int csplit,
              const bf16* __restrict__ src1,
              const bf16* __restrict__ img, int imgTileFloats, int C,
              const float* __restrict__ bias,
              float* __restrict__ cstate,
              bf16* __restrict__ hout)
{
    extern __shared__ __align__(1024) char smem[];
    uint32_t sb = (uint32_t)__cvta_generic_to_shared(smem);
    bf16* As = (bf16*)smem;                  // per stage: [64][LDA]
    bf16* Bs = (bf16*)(smem + B_OFF);        // per stage: [KC][LDB]
    float* bsm = (float*)(smem + BIAS_OFF);

    const int tid = threadIdx.x, wid = tid >> 5;
    const int bM = blockIdx.x * 64, tile = blockIdx.y;
    const int w_m = wid & 1, w_n = wid >> 1;  // warp tile 32x32 at (w_m*32, w_n*32)

    if (tid < 64) {
        int g = tid >> 4, ui = tid & 15;
        bsm[tid] = bias[g * UU + tile * 16 + ui];
    }

    const char* imgb = (const char*)(img + (size_t)tile * imgTileFloats);

    auto load_chunk = [&](int c, int slot) {
        // A: 64 rows x 64 halfs (128B/row = 8 x 16B) -> [m][LDA]
        const bf16* as; int lda, k0;
        if (c < csplit) { as = src0; lda = ld0; k0 = c * KC; }
        else            { as = src1; lda = UU;  k0 = (c - csplit) * KC; }
        uint32_t adst = sb + A_OFF + slot * A_STG;
#pragma unroll
        for (int j = 0; j < 4; j++) {
            int u = tid + 128 * j, m = u >> 3, kq = u & 7;
            CP_ASYNC16(adst + (uint32_t)(m * (LDA * 2) + kq * 16),
                       as + (size_t)(bM + m) * lda + k0 + kq * 8);
        }
        // B: verbatim packed [k 64][n 64] bf16 -> [k][LDB]
        const char* wsrc = imgb + (size_t)c * (KC * NCOL * 2);
        uint32_t bdst = sb + B_OFF + slot * B_STG;
#pragma unroll
        for (int j = 0; j < 4; j++) {
            int u = tid + 128 * j, k = u >> 3, nq = u & 7;
            CP_ASYNC16(bdst + (uint32_t)(k * (LDB * 2) + nq * 16), wsrc + u * 16);
        }
        CP_COMMIT();
    };

    wmma::fragment<wmma::accumulator, 16, 16, 16, float> acc[2][2];
#pragma unroll
    for (int i = 0; i < 2; i++)
#pragma unroll
        for (int j = 0; j < 2; j++) wmma::fill_fragment(acc[i][j], 0.f);

    load_chunk(0, 0);
    load_chunk(1, 1);

#pragma unroll 1
    for (int i = 0; i < C; i++) {
        CP_WAIT1();          // chunk i's group complete (<=1 outstanding: chunk i+1)
        __syncthreads();     // CTA-wide data ready; also: slot (i-1)%3 fully consumed
        int nc = i + 2;
        if (nc < C) load_chunk(nc, nc % STAGES);   // into slot (i-1)%3 — safe post-sync
        else        CP_COMMIT();                    // keep group accounting aligned

        const bf16* Ab = As + (i % STAGES) * (64 * LDA);
        const bf16* Bb = Bs + (i % STAGES) * (KC * LDB);
#pragma unroll
        for (int ks = 0; ks < 4; ks++) {
            const int kof = ks * 16;
            wmma::fragment<wmma::matrix_a, 16, 16, 16, bf16, wmma::row_major> af[2];
            wmma::fragment<wmma::matrix_b, 16, 16, 16, bf16, wmma::row_major> bf[2];
#pragma unroll
            for (int q = 0; q < 2; q++)
                wmma::load_matrix_sync(af[q], Ab + (w_m * 32 + 16 * q) * LDA + kof, LDA);
#pragma unroll
            for (int q = 0; q < 2; q++)
                wmma::load_matrix_sync(bf[q], Bb + kof * LDB + (w_n * 32 + 16 * q), LDB);
#pragma unroll
            for (int q = 0; q < 2; q++)
#pragma unroll
                for (int r = 0; r < 2; r++)
                    wmma::mma_sync(acc[q][r], af[q], bf[r], acc[q][r]);
        }
    }

    // ---- epilogue: stage z[64][64] f32 in smem (overlay A stages), then gate math ----
    __syncthreads();
    float* zs = (float*)smem;   // [64][LDZ] floats = 18432 B < A region (27648 B)
#pragma unroll
    for (int q = 0; q < 2; q++)
#pragma unroll
        for (int r = 0; r < 2; r++)
            wmma::store_matrix_sync(zs + (w_m * 32 + 16 * q) * LDZ + (w_n * 32 + 16 * r),
                                    acc[q][r], LDZ, wmma::mem_row_major);
    __syncthreads();

    const int u  = tid & 15;        // unit within tile
    const int b8 = tid >> 4;        // batch octet
    const int u0 = tile * 16;
    const float bi = bsm[u], bf_ = bsm[16 + u], bg = bsm[32 + u], bo = bsm[48 + u];

#pragma unroll
    for (int j = 0; j < 8; j++) {
        const int m = b8 * 8 + j;               // local batch row 0..63
        const size_t idx = (size_t)(bM + m) * UU + u0 + u;
        const float zi = zs[m * LDZ + u]       + bi;
        const float zf = zs[m * LDZ + 16 + u]  + bf_;
        const float zg = zs[m * LDZ + 32 + u]  + bg;
        const float zo = zs[m * LDZ + 48 + u]  + bo;
        const float ig = sigmoidf_(zi);
        const float fg = sigmoidf_(zf);
        const float gg = fmaxf(zg, 0.f);
        const float og = sigmoidf_(zo);
        const float c  = fg * cstate[idx] + ig * gg;
        cstate[idx] = c;
        hout[idx]   = __float2bfloat16_rn(og * fmaxf(c, 0.f));
    }
}

__global__ void head_kernel(const bf16* __restrict__ h2,
                            const float* __restrict__ Wd,
                            const float* __restrict__ bd,
                            float* __restrict__ out)
{
    const int b = threadIdx.x;
    float s = 0.f;
#pragma unroll 8
    for (int k = 0; k < UU; k++) s = fmaf(__bfloat162float(h2[b * UU + k]), Wd[k], s);
    out[b] = 1.f / (1.f + expf(-(s + bd[0])));
}

extern "C" void kernel_launch(void* const* d_in, const int* in_sizes, int n_in,
                              void* d_out, int out_size) {
    const float* x  = (const float*)d_in[0];
    const float* W1 = (const float*)d_in[1];
    const float* U1 = (const float*)d_in[2];
    const float* b1 = (const float*)d_in[3];
    const float* W2 = (const float*)d_in[4];
    const float* U2 = (const float*)d_in[5];
    const float* b2 = (const float*)d_in[6];
    const float* Wd = (const float*)d_in[7];
    const float* bd = (const float*)d_in[8];
    float* out = (float*)d_out;

    cudaFuncSetAttribute(lstm_step_mma, cudaFuncAttributeMaxDynamicSharedMemorySize, SMEM_BYTES);

    bf16 *xT, *img1, *img2, *h1b, *h2b;
    float *c1, *c2;
    cudaGetSymbolAddress((void**)&xT,   g_xT);
    cudaGetSymbolAddress((void**)&img1, g_img1);
    cudaGetSymbolAddress((void**)&img2, g_img2);
    cudaGetSymbolAddress((void**)&h1b,  g_h1);
    cudaGetSymbolAddress((void**)&c1,   g_c1);
    cudaGetSymbolAddress((void**)&h2b,  g_h2);
    cudaGetSymbolAddress((void**)&c2,   g_c2);
    bf16* h1[2] = { h1b, h1b + BB * UU };
    bf16* h2[2] = { h2b, h2b + BB * UU };

    zero_state_kernel<<<(BB * UU + 255) / 256, 256>>>();
    prep_x_kernel<<<(BB * TT * FF + 255) / 256, 256>>>(x);
    prep_img_kernel<<<(NTILES * 576 * NCOL + 255) / 256, 256>>>(W1, U1, img1, FF, 576);
    prep_img_kernel<<<(NTILES * 1024 * NCOL + 255) / 256, 256>>>(W2, U2, img2, UU, 1024);

    dim3 grid(BB / 64, NTILES);  // 4 x 32 = 128 CTAs
    for (int t = 0; t < TT; t++) {
        lstm_step_mma<<<grid, 128, SMEM_BYTES>>>(
            xT + t * BB * FF, FF, 1, h1[t & 1],
            img1, 576 * NCOL, 9, b1, c1, h1[(t + 1) & 1]);
        lstm_step_mma<<<grid, 128, SMEM_BYTES>>>(
            h1[(t + 1) & 1], UU, 8, h2[t & 1],
            img2, 1024 * NCOL, 16, b2, c2, h2[(t + 1) & 1]);
    }
    head_kernel<<<1, 256>>>(h2[0], Wd, bd, out);
}